// round 14
// baseline (speedup 1.0000x reference)
#include <cuda_runtime.h>
#include <cuda_bf16.h>
#include <cuda_fp16.h>
#include <math.h>
#include <stdint.h>

// Problem constants
#define NTOK 512
#define DD   128
#define NN   (NTOK*NTOK)

// Scratch (static __device__ arrays — no allocation allowed)
//   g_ab[arr][c][row*512+k] fp16: arr 0=left 1=right (single-rounded)
//   g_og  [c][j*512+i] fp16 sigmoid(out-gate)
//   g_mix [d][j*512+i] einsum result fp16
//   g_wfrag[w][kc][p][lane] uint4 — fp16 B-fragment-ready weights
__device__ __half        g_ab [67108864];
__device__ __half        g_og [33554432];
__device__ __half        g_mix[33554432];
__device__ __align__(16) uint4 g_wfrag[6 * 2048];

#define ARRSZ (128*NN)

// ---------------------------------------------------------------------------
// helpers
// ---------------------------------------------------------------------------
__device__ __forceinline__ uint32_t smem_u32(const void* p) {
    uint32_t a;
    asm("{ .reg .u64 t; cvta.to.shared.u64 t, %1; cvt.u32.u64 %0, t; }"
        : "=r"(a) : "l"(p));
    return a;
}

__device__ __forceinline__ void ldm4(uint32_t r[4], uint32_t addr) {
    asm volatile("ldmatrix.sync.aligned.m8n8.x4.shared.b16 {%0,%1,%2,%3}, [%4];"
                 : "=r"(r[0]), "=r"(r[1]), "=r"(r[2]), "=r"(r[3]) : "r"(addr));
}

__device__ __forceinline__ void mma_f16(float acc[4], const uint32_t a[4],
                                        uint32_t b0, uint32_t b1) {
    asm volatile(
        "mma.sync.aligned.m16n8k16.row.col.f32.f16.f16.f32 "
        "{%0,%1,%2,%3}, {%4,%5,%6,%7}, {%8,%9}, {%0,%1,%2,%3};"
        : "+f"(acc[0]), "+f"(acc[1]), "+f"(acc[2]), "+f"(acc[3])
        : "r"(a[0]), "r"(a[1]), "r"(a[2]), "r"(a[3]), "r"(b0), "r"(b1));
}

#define CPASYNC16(dst, src) \
    asm volatile("cp.async.cg.shared.global [%0], [%1], 16;" \
                 :: "r"(dst), "l"(src) : "memory")
#define CPCOMMIT() asm volatile("cp.async.commit_group;" ::: "memory")
#define CPWAIT1()  asm volatile("cp.async.wait_group 1;" ::: "memory")
#define CPWAIT0()  asm volatile("cp.async.wait_group 0;" ::: "memory")

__device__ __forceinline__ float sigmoidf_(float z) {
    return 1.f / (1.f + expf(-z));
}

// ---------------------------------------------------------------------------
// Kernel 0: weights -> fp16 B-fragment layout, register-ready for mma.sync.
// ---------------------------------------------------------------------------
__global__ void wprep_kernel(const float* __restrict__ W0, const float* __restrict__ W1,
                             const float* __restrict__ W2, const float* __restrict__ W3,
                             const float* __restrict__ W4, const float* __restrict__ W5)
{
    const float* W = (blockIdx.x == 0) ? W0 : (blockIdx.x == 1) ? W1 :
                     (blockIdx.x == 2) ? W2 : (blockIdx.x == 3) ? W3 :
                     (blockIdx.x == 4) ? W4 : W5;
    uint4* dst = g_wfrag + blockIdx.x * 2048;
    for (int idx = threadIdx.x; idx < 2048; idx += 256) {
        const int lane = idx & 31;
        const int p    = (idx >> 5) & 7;
        const int kc   = idx >> 8;
        const int nf = p * 16 + (lane >> 2);
        const int k0 = kc * 16 + 2 * (lane & 3);
        uint16_t e[8];
        #pragma unroll
        for (int q = 0; q < 8; ++q) {
            const int k = k0 + (q & 1) + ((q >> 1) & 1) * 8;
            const int n = nf + (q >> 2) * 8;
            __half h = __float2half_rn(W[k * 128 + n]);
            e[q] = *(uint16_t*)&h;
        }
        uint4 o;
        o.x = (uint32_t)e[0] | ((uint32_t)e[1] << 16);
        o.y = (uint32_t)e[2] | ((uint32_t)e[3] << 16);
        o.z = (uint32_t)e[4] | ((uint32_t)e[5] << 16);
        o.w = (uint32_t)e[6] | ((uint32_t)e[7] << 16);
        dst[idx] = o;
    }
}

// ---------------------------------------------------------------------------
// Kernel 1: LayerNorm + 5 projections (fp16 single-A MMA, fused value+gate).
// 64-row blocks, 8 warps 2m x 4n, 3 CTAs/SM (smem ~50.7KB).
// MODE: 1 = value+gate (store gated value single fp16), 2 = out-gate
// ---------------------------------------------------------------------------
#define K1_AH   0
#define K1_ST   17408
#define K1_MS   50432
#define K1_SMEM 50688

template<int MODE>
__device__ __forceinline__ void k1_pass2(
    char* sm1, uint32_t sb, int wv, int wg,
    const float* __restrict__ bv, const float* __restrict__ bg,
    int tid, int lane, int wm, int wn,
    __half* dst, size_t gbase)
{
    constexpr bool PAIR = (MODE == 1);
    const int g = lane >> 3, r = lane & 7;
    uint32_t aoffH[2];
    #pragma unroll
    for (int mi = 0; mi < 2; ++mi)
        aoffH[mi] = sb + K1_AH +
            (uint32_t)((wm + mi*16 + r + (g&1)*8) * 272 + ((g>>1)*8)*2);
    const uint4* __restrict__ fv = g_wfrag + wv * 2048 + lane;
    const uint4* __restrict__ fg = g_wfrag + wg * 2048 + lane;
    const int pbase = wn >> 4;

    float accV[2][4][4] = {};
    float accG[PAIR ? 2 : 1][4][4] = {};

    #pragma unroll
    for (int kc = 0; kc < 8; ++kc) {
        uint32_t AH[2][4];
        #pragma unroll
        for (int mi = 0; mi < 2; ++mi)
            ldm4(AH[mi], aoffH[mi] + kc*32);
        #pragma unroll
        for (int p4 = 0; p4 < 2; ++p4) {
            const int fidx = (kc*8 + pbase + p4) * 32;
            const uint4 bv4 = fv[fidx];
            uint4 bg4;
            if (PAIR) bg4 = fg[fidx];
            #pragma unroll
            for (int ns = 0; ns < 2; ++ns) {
                const int ni = p4*2 + ns;
                const uint32_t v0 = ns ? bv4.z : bv4.x, v1 = ns ? bv4.w : bv4.y;
                #pragma unroll
                for (int mi = 0; mi < 2; ++mi)
                    mma_f16(accV[mi][ni], AH[mi], v0, v1);
                if (PAIR) {
                    const uint32_t g0 = ns ? bg4.z : bg4.x, g1 = ns ? bg4.w : bg4.y;
                    #pragma unroll
                    for (int mi = 0; mi < 2; ++mi)
                        mma_f16(accG[mi][ni], AH[mi], g0, g1);
                }
            }
        }
    }

    float* stagef = (float*)(sm1 + K1_ST);
    const float* mask_s = (const float*)(sm1 + K1_MS);

    #pragma unroll
    for (int mi = 0; mi < 2; ++mi)
        #pragma unroll
        for (int ni = 0; ni < 4; ++ni) {
            const int m0 = wm + mi*16 + (lane >> 2);
            const int n  = wn + ni*8 + (lane & 3)*2;
            const float b0 = __ldg(bv + n), b1 = __ldg(bv + n + 1);
            float* a = accV[mi][ni];
            if (PAIR) {
                const float c0 = __ldg(bg + n), c1 = __ldg(bg + n + 1);
                const float* gacc = accG[mi][ni];
                const float mk0 = mask_s[m0], mk1 = mask_s[m0 + 8];
                stagef[ m0   *129 + n    ] = (a[0]+b0)*mk0*sigmoidf_(gacc[0]+c0);
                stagef[ m0   *129 + n + 1] = (a[1]+b1)*mk0*sigmoidf_(gacc[1]+c1);
                stagef[(m0+8)*129 + n    ] = (a[2]+b0)*mk1*sigmoidf_(gacc[2]+c0);
                stagef[(m0+8)*129 + n + 1] = (a[3]+b1)*mk1*sigmoidf_(gacc[3]+c1);
            } else {
                stagef[ m0   *129 + n    ] = sigmoidf_(a[0] + b0);
                stagef[ m0   *129 + n + 1] = sigmoidf_(a[1] + b1);
                stagef[(m0+8)*129 + n    ] = sigmoidf_(a[2] + b0);
                stagef[(m0+8)*129 + n + 1] = sigmoidf_(a[3] + b1);
            }
        }
    __syncthreads();

    #pragma unroll
    for (int it = 0; it < 8; ++it) {
        const int idx = it * 256 + tid;        // 2048 = 128c x 16 row-quads
        const int c  = idx >> 4;
        const int rq = (idx & 15) * 4;
        __half2 a = __floats2half2_rn(stagef[(rq  )*129 + c], stagef[(rq+1)*129 + c]);
        __half2 b = __floats2half2_rn(stagef[(rq+2)*129 + c], stagef[(rq+3)*129 + c]);
        uint2 o;
        *(__half2*)&o.x = a;
        *(__half2*)&o.y = b;
        *(uint2*)(dst + (size_t)c * NN + gbase + rq) = o;
    }
    __syncthreads();
}

__global__ __launch_bounds__(256, 3) void ln_proj_mma_kernel(
    const float* __restrict__ x,   const float* __restrict__ msk,
    const float* __restrict__ nsc, const float* __restrict__ nbi,
    const float* __restrict__ bl,  const float* __restrict__ br,
    const float* __restrict__ blg, const float* __restrict__ brg,
    const float* __restrict__ bog)
{
    extern __shared__ __align__(16) char sm1[];
    const int tid  = threadIdx.x;
    const int lane = tid & 31;
    const int wid  = tid >> 5;
    const int n2   = blockIdx.x & 511;
    const int n1b  = (blockIdx.x >> 9) << 6;
    const uint32_t sb = smem_u32(sm1);

    // ---- LayerNorm prologue: single fp16 A into smem ----
    {
        const int row = tid >> 2, sub = tid & 3;
        const float4* xr = reinterpret_cast<const float4*>(
                               x + ((size_t)(n1b + row) * 512 + n2) * DD) + sub * 8;
        float4 v[8];
        float s = 0.f, ss = 0.f;
        #pragma unroll
        for (int q = 0; q < 8; ++q) {
            v[q] = xr[q];
            s  += v[q].x + v[q].y + v[q].z + v[q].w;
            ss += v[q].x*v[q].x + v[q].y*v[q].y + v[q].z*v[q].z + v[q].w*v[q].w;
        }
        s  += __shfl_xor_sync(0xffffffffu, s, 1);
        ss += __shfl_xor_sync(0xffffffffu, ss, 1);
        s  += __shfl_xor_sync(0xffffffffu, s, 2);
        ss += __shfl_xor_sync(0xffffffffu, ss, 2);
        const float mu   = s * (1.f/128.f);
        const float var  = ss * (1.f/128.f) - mu*mu;
        const float rstd = rsqrtf(var + 1e-6f);
        #pragma unroll
        for (int q = 0; q < 8; ++q) {
            const int d0 = sub*32 + q*4;
            float a0 = (v[q].x - mu)*rstd*__ldg(&nsc[d0+0]) + __ldg(&nbi[d0+0]);
            float a1 = (v[q].y - mu)*rstd*__ldg(&nsc[d0+1]) + __ldg(&nbi[d0+1]);
            float a2 = (v[q].z - mu)*rstd*__ldg(&nsc[d0+2]) + __ldg(&nbi[d0+2]);
            float a3 = (v[q].w - mu)*rstd*__ldg(&nsc[d0+3]) + __ldg(&nbi[d0+3]);
            __half2 h01 = __floats2half2_rn(a0, a1);
            __half2 h23 = __floats2half2_rn(a2, a3);
            uint2 hw;
            *(__half2*)&hw.x = h01;
            *(__half2*)&hw.y = h23;
            *(uint2*)(sm1 + K1_AH + row*272 + d0*2) = hw;
        }
        if (sub == 0)
            ((float*)(sm1 + K1_MS))[row] = msk[n1b + row] * msk[n2];
    }
    __syncthreads();

    const int wm = (wid & 1) * 32;
    const int wn = (wid >> 1) * 32;
    const size_t gbase = (size_t)n2 * 512 + n1b;

    k1_pass2<1>(sm1, sb, 1, 0, bl,  blg, tid, lane, wm, wn, g_ab,         gbase);
    k1_pass2<1>(sm1, sb, 3, 2, br,  brg, tid, lane, wm, wn, g_ab + ARRSZ, gbase);
    k1_pass2<2>(sm1, sb, 4, 4, bog, bog, tid, lane, wm, wn, g_og,         gbase);
}

// ---------------------------------------------------------------------------
// Kernel 2: einsum via mma.sync fp16 single x single (1 MMA per k16-step).
// 128x64 tiles, cp.async 3-stage ring, ONE sync per K-iteration, 3 CTAs/SM.
// ---------------------------------------------------------------------------
#define E3_STAGE 15360
#define E3_SMEM  46080

__global__ __launch_bounds__(256, 3) void einsum_mma_kernel()
{
    extern __shared__ __align__(16) char esm[];
    const int tid  = threadIdx.x;
    const int lane = tid & 31;
    const int wid  = tid >> 5;
    const int d    = blockIdx.y;
    const int i0   = (blockIdx.x & 3) * 128;
    const int j0   = (blockIdx.x >> 2) * 64;
    const uint32_t sbm = smem_u32(esm);

    const __half* __restrict__ base = g_ab + (size_t)d * NN;

    uint32_t goff[3], soff[3];
    #pragma unroll
    for (int it = 0; it < 3; ++it) {
        int arr, rem;
        if (it < 2) { arr = 0; rem = it * 256 + tid; }
        else        { arr = 1; rem = tid; }
        const int row = rem >> 2, seg = rem & 3;
        const int r0 = (arr == 0) ? i0 : j0;
        const uint32_t ab = (arr == 0) ? 0u : 10240u;
        goff[it] = (uint32_t)(arr * ARRSZ) + (uint32_t)((r0 + row)*512 + seg*8);
        soff[it] = ab + (uint32_t)(row*80 + seg*16);
    }

    const int g = lane >> 3, r = lane & 7;
    const int wm = (wid & 3) * 32;
    const int wn = (wid >> 2) * 32;
    uint32_t aoff[2], boff[2];
    #pragma unroll
    for (int mi = 0; mi < 2; ++mi)
        aoff[mi] = sbm + (uint32_t)((wm + mi*16 + r + (g&1)*8)*80 + ((g>>1)*8)*2);
    #pragma unroll
    for (int p = 0; p < 2; ++p)
        boff[p] = sbm + 10240 + (uint32_t)((wn + p*16 + r + (g>>1)*8)*80 + ((g&1)*8)*2);

    float acc[2][4][4] = {};

    #pragma unroll
    for (int it = 0; it < 3; ++it)
        CPASYNC16(sbm + soff[it], base + goff[it]);
    CPCOMMIT();
    #pragma unroll
    for (int it = 0; it < 3; ++it)
        CPASYNC16(sbm + E3_STAGE + soff[it], base + goff[it] + 32);
    CPCOMMIT();

    #pragma unroll 1
    for (int kc = 0; kc < 16; ++kc) {
        if (kc < 15) { CPWAIT1(); } else { CPWAIT0(); }
        __syncthreads();

        if (kc < 14) {
            const uint32_t nstg = (uint32_t)((kc + 2) % 3) * E3_STAGE;
            const int kb = (kc + 2) * 32;
            #pragma unroll
            for (int it = 0; it < 3; ++it)
                CPASYNC16(sbm + nstg + soff[it], base + goff[it] + kb);
            CPCOMMIT();
        }

        const uint32_t stg = (uint32_t)(kc % 3) * E3_STAGE;
        #pragma unroll
        for (int ks2 = 0; ks2 < 2; ++ks2) {
            const uint32_t off = stg + (uint32_t)ks2 * 32;
            uint32_t A[2][4], B[2][4];
            #pragma unroll
            for (int mi = 0; mi < 2; ++mi)
                ldm4(A[mi], aoff[mi] + off);
            #pragma unroll
            for (int p = 0; p < 2; ++p)
                ldm4(B[p], boff[p] + off);
            #pragma unroll
            for (int mi = 0; mi < 2; ++mi)
                #pragma unroll
                for (int ni = 0; ni < 4; ++ni) {
                    const int p = ni >> 1, h = (ni & 1) * 2;
                    mma_f16(acc[mi][ni], A[mi], B[p][h], B[p][h+1]);
                }
        }
    }
    __syncthreads();

    float* smT = (float*)esm;   // [64][132]
    #pragma unroll
    for (int mi = 0; mi < 2; ++mi)
        #pragma unroll
        for (int ni = 0; ni < 4; ++ni) {
            const int m = wm + mi*16 + (lane >> 2);
            const int j = wn + ni*8 + (lane & 3)*2;
            smT[(j  )*132 + m    ] = acc[mi][ni][0];
            smT[(j+1)*132 + m    ] = acc[mi][ni][1];
            smT[(j  )*132 + m + 8] = acc[mi][ni][2];
            smT[(j+1)*132 + m + 8] = acc[mi][ni][3];
        }
    __syncthreads();

    __half* gm = g_mix + (size_t)d * NN;
    #pragma unroll
    for (int it = 0; it < 8; ++it) {
        const int idx = it*256 + tid;
        const int j = idx >> 5, c4 = idx & 31;
        __half2 h0 = __floats2half2_rn(smT[j*132 + c4*4 + 0], smT[j*132 + c4*4 + 1]);
        __half2 h1 = __floats2half2_rn(smT[j*132 + c4*4 + 2], smT[j*132 + c4*4 + 3]);
        uint2 o;
        *(__half2*)&o.x = h0;
        *(__half2*)&o.y = h1;
        *(uint2*)(gm + (size_t)(j0 + j)*512 + i0 + c4*4) = o;
    }
}

// ---------------------------------------------------------------------------
// Kernel 3: out-LN (over d) * out_gate, then @ W_out + b_out — single-A fp16.
// g_mix fp16 read twice (2nd hits L2). 4 CTAs/SM.
// ---------------------------------------------------------------------------
#define O_AH    0
#define O_RED   17408
#define O_SMEM  36864      // stage [64][132] f32 = 33792 overlays AH+red

__global__ __launch_bounds__(256, 4) void out_mma_kernel(
    const float* __restrict__ gs, const float* __restrict__ gb,
    const float* __restrict__ bout, float* __restrict__ out)
{
    extern __shared__ __align__(16) char sm3[];
    const int tid  = threadIdx.x;
    const int lane = tid & 31;
    const int wid  = tid >> 5;
    const int rt0  = blockIdx.x * 64;
    const int j    = rt0 >> 9;
    const int ibase = rt0 & 511;
    const uint32_t sb = smem_u32(sm3);

    float* red = (float*)(sm3 + O_RED);

    const int rt_l = tid & 63;
    const int qtr  = tid >> 6;
    const int d0   = qtr * 32;

    float s = 0.f, q = 0.f;
    #pragma unroll 8
    for (int dd = d0; dd < d0 + 32; ++dd) {
        float v = __half2float(g_mix[(size_t)dd*NN + rt0 + rt_l]);
        s += v; q += v*v;
    }
    red[qtr*64 + rt_l]       = s;
    red[256 + qtr*64 + rt_l] = q;
    __syncthreads();
    const float S = red[rt_l] + red[64 + rt_l] + red[128 + rt_l] + red[192 + rt_l];
    const float Q = red[256 + rt_l] + red[320 + rt_l] + red[384 + rt_l] + red[448 + rt_l];
    const float mu   = S * (1.f/128.f);
    const float rstd = rsqrtf(Q * (1.f/128.f) - mu*mu + 1e-6f);

    #pragma unroll 4
    for (int dd = d0; dd < d0 + 32; dd += 2) {
        float v0 = __half2float(g_mix[(size_t) dd     *NN + rt0 + rt_l]);
        float v1 = __half2float(g_mix[(size_t)(dd + 1)*NN + rt0 + rt_l]);
        float o0 = __half2float(g_og[(size_t) dd     *NN + rt0 + rt_l]);
        float o1 = __half2float(g_og[(size_t)(dd + 1)*NN + rt0 + rt_l]);
        float g0 = ((v0 - mu)*rstd*__ldg(gs+dd)   + __ldg(gb+dd))   * o0;
        float g1 = ((v1 - mu)*rstd*__ldg(gs+dd+1) + __ldg(gb+dd+1)) * o1;
        __half2 h2 = __floats2half2_rn(g0, g1);
        *(__half2*)(sm3 + O_AH + rt_l*272 + dd*2) = h2;
    }
    __syncthreads();

    const int g = lane >> 3, r = lane & 7;
    const int wm = (wid & 1) * 32;
    const int wn = (wid >> 1) * 32;
    uint32_t aoffH[2];
    #pragma unroll
    for (int mi = 0; mi < 2; ++mi)
        aoffH[mi] = sb + O_AH +
            (uint32_t)((wm + mi*16 + r + (g&1)*8) * 272 + ((g>>1)*8)*2);
    const uint4* __restrict__ fw = g_wfrag + 5 * 2048 + lane;
    const int pbase = wn >> 4;

    float acc[2][4][4] = {};
    #pragma unroll
    for (int kc = 0; kc < 8; ++kc) {
        uint32_t AH[2][4];
        #pragma unroll
        for (int mi = 0; mi < 2; ++mi)
            ldm4(AH[mi], aoffH[mi] + kc*32);
        #pragma unroll
        for (int p4 = 0; p4 < 2; ++p4) {
            const uint4 bh = fw[(kc*8 + pbase + p4) * 32];
            #pragma unroll
            for (int ns = 0; ns < 2; ++ns) {
                const int ni = p4*2 + ns;
                const uint32_t h0 = ns ? bh.z : bh.x, h1 = ns ? bh.w : bh.y;
                #pragma unroll
                for (int mi = 0; mi < 2; ++mi)
                    mma_f16(acc[mi][ni], AH[mi], h0, h1);
            }
        }
    }
    __syncthreads();   // A reads done; stage overlays AH+red region

    float* stagef = (float*)(sm3 + O_AH);   // [64][132] f32
    #pragma unroll
    for (int mi = 0; mi < 2; ++mi)
        #pragma unroll
        for (int ni = 0; ni < 4; ++ni) {
            const int m0 = wm + mi*16 + (lane >> 2);
            const int n  = wn + ni*8 + (lane & 3)*2;
            const float b0 = __ldg(bout + n), b1 = __ldg(bout + n + 1);
            stagef[ m0   *132 + n    ] = acc[mi][ni][0] + b0;
            stagef[ m0   *132 + n + 1] = acc[mi][ni][1] + b1;
            stagef[(m0+8)*132 + n    ] = acc[mi][ni][2] + b0;
            stagef[(m0+8)*132 + n + 1] = acc[mi][ni][3] + b1;
        }
    __syncthreads();

    #pragma unroll
    for (int it = 0; it < 8; ++it) {
        const int idx = it * 256 + tid;
        const int row = idx >> 5, c4 = idx & 31;
        float4 v;
        v.x = stagef[row*132 + c4*4 + 0];
        v.y = stagef[row*132 + c4*4 + 1];
        v.z = stagef[row*132 + c4*4 + 2];
        v.w = stagef[row*132 + c4*4 + 3];
        *reinterpret_cast<float4*>(
            out + ((size_t)(ibase + row)*512 + j)*DD + c4*4) = v;
    }
}

// ---------------------------------------------------------------------------
extern "C" void kernel_launch(void* const* d_in, const int* in_sizes, int n_in,
                              void* d_out, int out_size)
{
    const float* x    = (const float*)d_in[0];
    const float* mskp = (const float*)d_in[1];
    const float* nsc  = (const float*)d_in[2];
    const float* nbi  = (const float*)d_in[3];
    const float* Wl   = (const float*)d_in[4];
    const float* bl   = (const float*)d_in[5];
    const float* Wr   = (const float*)d_in[6];
    const float* br   = (const float*)d_in[7];
    const float* Wlg  = (const float*)d_in[8];
    const float* blg  = (const float*)d_in[9];
    const float* Wrg  = (const float*)d_in[10];
    const float* brg  = (const float*)d_in[11];
    const float* Wog  = (const float*)d_in[12];
    const float* bog  = (const float*)d_in[13];
    const float* gs   = (const float*)d_in[14];
    const float* gb   = (const float*)d_in[15];
    const float* Wout = (const float*)d_in[16];
    const float* bout = (const float*)d_in[17];
    float* out = (float*)d_out;

    cudaFuncSetAttribute(einsum_mma_kernel,
                         cudaFuncAttributeMaxDynamicSharedMemorySize, E3_SMEM);
    cudaFuncSetAttribute(ln_proj_mma_kernel,
                         cudaFuncAttributeMaxDynamicSharedMemorySize, K1_SMEM);
    cudaFuncSetAttribute(out_mma_kernel,
                         cudaFuncAttributeMaxDynamicSharedMemorySize, O_SMEM);

    wprep_kernel<<<6, 256>>>(Wlg, Wl, Wrg, Wr, Wog, Wout);
    ln_proj_mma_kernel<<<4096, 256, K1_SMEM>>>(x, mskp, nsc, nbi,
                                               bl, br, blg, brg, bog);
    einsum_mma_kernel<<<dim3(32, 128), 256, E3_SMEM>>>();
    out_mma_kernel<<<4096, 256, O_SMEM>>>(gs, gb, bout, out);
}

// round 15
// speedup vs baseline: 1.6167x; 1.6167x over previous
#include <cuda_runtime.h>
#include <cuda_bf16.h>
#include <cuda_fp16.h>
#include <math.h>
#include <stdint.h>

// Problem constants
#define NTOK 512
#define DD   128
#define NN   (NTOK*NTOK)

// Scratch (static __device__ arrays — no allocation allowed)
//   g_ab[arr][c][row*512+k] fp16: arr 0=left 1=right (single-rounded)
//   g_og  [c][j*512+i] fp16 sigmoid(out-gate)
//   g_mix [d][j*512+i] einsum result fp16
//   g_wfrag[w][kc][p][lane] uint4 — fp16 B-fragment-ready weights
__device__ __half        g_ab [67108864];
__device__ __half        g_og [33554432];
__device__ __half        g_mix[33554432];
__device__ __align__(16) uint4 g_wfrag[6 * 2048];

#define ARRSZ (128*NN)

// ---------------------------------------------------------------------------
// helpers
// ---------------------------------------------------------------------------
__device__ __forceinline__ uint32_t smem_u32(const void* p) {
    uint32_t a;
    asm("{ .reg .u64 t; cvta.to.shared.u64 t, %1; cvt.u32.u64 %0, t; }"
        : "=r"(a) : "l"(p));
    return a;
}

__device__ __forceinline__ void ldm4(uint32_t r[4], uint32_t addr) {
    asm volatile("ldmatrix.sync.aligned.m8n8.x4.shared.b16 {%0,%1,%2,%3}, [%4];"
                 : "=r"(r[0]), "=r"(r[1]), "=r"(r[2]), "=r"(r[3]) : "r"(addr));
}

__device__ __forceinline__ void mma_f16(float acc[4], const uint32_t a[4],
                                        uint32_t b0, uint32_t b1) {
    asm volatile(
        "mma.sync.aligned.m16n8k16.row.col.f32.f16.f16.f32 "
        "{%0,%1,%2,%3}, {%4,%5,%6,%7}, {%8,%9}, {%0,%1,%2,%3};"
        : "+f"(acc[0]), "+f"(acc[1]), "+f"(acc[2]), "+f"(acc[3])
        : "r"(a[0]), "r"(a[1]), "r"(a[2]), "r"(a[3]), "r"(b0), "r"(b1));
}

#define CPASYNC16(dst, src) \
    asm volatile("cp.async.cg.shared.global [%0], [%1], 16;" \
                 :: "r"(dst), "l"(src) : "memory")
#define CPCOMMIT() asm volatile("cp.async.commit_group;" ::: "memory")
#define CPWAIT1()  asm volatile("cp.async.wait_group 1;" ::: "memory")
#define CPWAIT0()  asm volatile("cp.async.wait_group 0;" ::: "memory")

__device__ __forceinline__ float sigmoidf_(float z) {
    return 1.f / (1.f + expf(-z));
}

// ---------------------------------------------------------------------------
// Kernel 0: weights -> fp16 B-fragment layout, register-ready for mma.sync.
// ---------------------------------------------------------------------------
__global__ void wprep_kernel(const float* __restrict__ W0, const float* __restrict__ W1,
                             const float* __restrict__ W2, const float* __restrict__ W3,
                             const float* __restrict__ W4, const float* __restrict__ W5)
{
    const float* W = (blockIdx.x == 0) ? W0 : (blockIdx.x == 1) ? W1 :
                     (blockIdx.x == 2) ? W2 : (blockIdx.x == 3) ? W3 :
                     (blockIdx.x == 4) ? W4 : W5;
    uint4* dst = g_wfrag + blockIdx.x * 2048;
    for (int idx = threadIdx.x; idx < 2048; idx += 256) {
        const int lane = idx & 31;
        const int p    = (idx >> 5) & 7;
        const int kc   = idx >> 8;
        const int nf = p * 16 + (lane >> 2);
        const int k0 = kc * 16 + 2 * (lane & 3);
        uint16_t e[8];
        #pragma unroll
        for (int q = 0; q < 8; ++q) {
            const int k = k0 + (q & 1) + ((q >> 1) & 1) * 8;
            const int n = nf + (q >> 2) * 8;
            __half h = __float2half_rn(W[k * 128 + n]);
            e[q] = *(uint16_t*)&h;
        }
        uint4 o;
        o.x = (uint32_t)e[0] | ((uint32_t)e[1] << 16);
        o.y = (uint32_t)e[2] | ((uint32_t)e[3] << 16);
        o.z = (uint32_t)e[4] | ((uint32_t)e[5] << 16);
        o.w = (uint32_t)e[6] | ((uint32_t)e[7] << 16);
        dst[idx] = o;
    }
}

// ---------------------------------------------------------------------------
// Kernel 1: LayerNorm + 5 projections (fp16 single-A MMA, fused value+gate).
// 64-row blocks, 8 warps 2m x 4n, 2 CTAs/SM (128-reg cap: no spills —
// minBlocks=3 capped regs at 84 and spilled the 64 accumulators; reverted).
// MODE: 1 = value+gate (store gated value single fp16), 2 = out-gate
// ---------------------------------------------------------------------------
#define K1_AH   0
#define K1_ST   17408
#define K1_MS   50432
#define K1_SMEM 50688

template<int MODE>
__device__ __forceinline__ void k1_pass2(
    char* sm1, uint32_t sb, int wv, int wg,
    const float* __restrict__ bv, const float* __restrict__ bg,
    int tid, int lane, int wm, int wn,
    __half* dst, size_t gbase)
{
    constexpr bool PAIR = (MODE == 1);
    const int g = lane >> 3, r = lane & 7;
    uint32_t aoffH[2];
    #pragma unroll
    for (int mi = 0; mi < 2; ++mi)
        aoffH[mi] = sb + K1_AH +
            (uint32_t)((wm + mi*16 + r + (g&1)*8) * 272 + ((g>>1)*8)*2);
    const uint4* __restrict__ fv = g_wfrag + wv * 2048 + lane;
    const uint4* __restrict__ fg = g_wfrag + wg * 2048 + lane;
    const int pbase = wn >> 4;

    float accV[2][4][4] = {};
    float accG[PAIR ? 2 : 1][4][4] = {};

    #pragma unroll
    for (int kc = 0; kc < 8; ++kc) {
        uint32_t AH[2][4];
        #pragma unroll
        for (int mi = 0; mi < 2; ++mi)
            ldm4(AH[mi], aoffH[mi] + kc*32);
        #pragma unroll
        for (int p4 = 0; p4 < 2; ++p4) {
            const int fidx = (kc*8 + pbase + p4) * 32;
            const uint4 bv4 = fv[fidx];
            uint4 bg4;
            if (PAIR) bg4 = fg[fidx];
            #pragma unroll
            for (int ns = 0; ns < 2; ++ns) {
                const int ni = p4*2 + ns;
                const uint32_t v0 = ns ? bv4.z : bv4.x, v1 = ns ? bv4.w : bv4.y;
                #pragma unroll
                for (int mi = 0; mi < 2; ++mi)
                    mma_f16(accV[mi][ni], AH[mi], v0, v1);
                if (PAIR) {
                    const uint32_t g0 = ns ? bg4.z : bg4.x, g1 = ns ? bg4.w : bg4.y;
                    #pragma unroll
                    for (int mi = 0; mi < 2; ++mi)
                        mma_f16(accG[mi][ni], AH[mi], g0, g1);
                }
            }
        }
    }

    float* stagef = (float*)(sm1 + K1_ST);
    const float* mask_s = (const float*)(sm1 + K1_MS);

    #pragma unroll
    for (int mi = 0; mi < 2; ++mi)
        #pragma unroll
        for (int ni = 0; ni < 4; ++ni) {
            const int m0 = wm + mi*16 + (lane >> 2);
            const int n  = wn + ni*8 + (lane & 3)*2;
            const float b0 = __ldg(bv + n), b1 = __ldg(bv + n + 1);
            float* a = accV[mi][ni];
            if (PAIR) {
                const float c0 = __ldg(bg + n), c1 = __ldg(bg + n + 1);
                const float* gacc = accG[mi][ni];
                const float mk0 = mask_s[m0], mk1 = mask_s[m0 + 8];
                stagef[ m0   *129 + n    ] = (a[0]+b0)*mk0*sigmoidf_(gacc[0]+c0);
                stagef[ m0   *129 + n + 1] = (a[1]+b1)*mk0*sigmoidf_(gacc[1]+c1);
                stagef[(m0+8)*129 + n    ] = (a[2]+b0)*mk1*sigmoidf_(gacc[2]+c0);
                stagef[(m0+8)*129 + n + 1] = (a[3]+b1)*mk1*sigmoidf_(gacc[3]+c1);
            } else {
                stagef[ m0   *129 + n    ] = sigmoidf_(a[0] + b0);
                stagef[ m0   *129 + n + 1] = sigmoidf_(a[1] + b1);
                stagef[(m0+8)*129 + n    ] = sigmoidf_(a[2] + b0);
                stagef[(m0+8)*129 + n + 1] = sigmoidf_(a[3] + b1);
            }
        }
    __syncthreads();

    #pragma unroll
    for (int it = 0; it < 8; ++it) {
        const int idx = it * 256 + tid;        // 2048 = 128c x 16 row-quads
        const int c  = idx >> 4;
        const int rq = (idx & 15) * 4;
        __half2 a = __floats2half2_rn(stagef[(rq  )*129 + c], stagef[(rq+1)*129 + c]);
        __half2 b = __floats2half2_rn(stagef[(rq+2)*129 + c], stagef[(rq+3)*129 + c]);
        uint2 o;
        *(__half2*)&o.x = a;
        *(__half2*)&o.y = b;
        *(uint2*)(dst + (size_t)c * NN + gbase + rq) = o;
    }
    __syncthreads();
}

__global__ __launch_bounds__(256, 2) void ln_proj_mma_kernel(
    const float* __restrict__ x,   const float* __restrict__ msk,
    const float* __restrict__ nsc, const float* __restrict__ nbi,
    const float* __restrict__ bl,  const float* __restrict__ br,
    const float* __restrict__ blg, const float* __restrict__ brg,
    const float* __restrict__ bog)
{
    extern __shared__ __align__(16) char sm1[];
    const int tid  = threadIdx.x;
    const int lane = tid & 31;
    const int wid  = tid >> 5;
    const int n2   = blockIdx.x & 511;
    const int n1b  = (blockIdx.x >> 9) << 6;
    const uint32_t sb = smem_u32(sm1);

    // ---- LayerNorm prologue: single fp16 A into smem ----
    {
        const int row = tid >> 2, sub = tid & 3;
        const float4* xr = reinterpret_cast<const float4*>(
                               x + ((size_t)(n1b + row) * 512 + n2) * DD) + sub * 8;
        float4 v[8];
        float s = 0.f, ss = 0.f;
        #pragma unroll
        for (int q = 0; q < 8; ++q) {
            v[q] = xr[q];
            s  += v[q].x + v[q].y + v[q].z + v[q].w;
            ss += v[q].x*v[q].x + v[q].y*v[q].y + v[q].z*v[q].z + v[q].w*v[q].w;
        }
        s  += __shfl_xor_sync(0xffffffffu, s, 1);
        ss += __shfl_xor_sync(0xffffffffu, ss, 1);
        s  += __shfl_xor_sync(0xffffffffu, s, 2);
        ss += __shfl_xor_sync(0xffffffffu, ss, 2);
        const float mu   = s * (1.f/128.f);
        const float var  = ss * (1.f/128.f) - mu*mu;
        const float rstd = rsqrtf(var + 1e-6f);
        #pragma unroll
        for (int q = 0; q < 8; ++q) {
            const int d0 = sub*32 + q*4;
            float a0 = (v[q].x - mu)*rstd*__ldg(&nsc[d0+0]) + __ldg(&nbi[d0+0]);
            float a1 = (v[q].y - mu)*rstd*__ldg(&nsc[d0+1]) + __ldg(&nbi[d0+1]);
            float a2 = (v[q].z - mu)*rstd*__ldg(&nsc[d0+2]) + __ldg(&nbi[d0+2]);
            float a3 = (v[q].w - mu)*rstd*__ldg(&nsc[d0+3]) + __ldg(&nbi[d0+3]);
            __half2 h01 = __floats2half2_rn(a0, a1);
            __half2 h23 = __floats2half2_rn(a2, a3);
            uint2 hw;
            *(__half2*)&hw.x = h01;
            *(__half2*)&hw.y = h23;
            *(uint2*)(sm1 + K1_AH + row*272 + d0*2) = hw;
        }
        if (sub == 0)
            ((float*)(sm1 + K1_MS))[row] = msk[n1b + row] * msk[n2];
    }
    __syncthreads();

    const int wm = (wid & 1) * 32;
    const int wn = (wid >> 1) * 32;
    const size_t gbase = (size_t)n2 * 512 + n1b;

    k1_pass2<1>(sm1, sb, 1, 0, bl,  blg, tid, lane, wm, wn, g_ab,         gbase);
    k1_pass2<1>(sm1, sb, 3, 2, br,  brg, tid, lane, wm, wn, g_ab + ARRSZ, gbase);
    k1_pass2<2>(sm1, sb, 4, 4, bog, bog, tid, lane, wm, wn, g_og,         gbase);
}

// ---------------------------------------------------------------------------
// Kernel 2: einsum via mma.sync fp16 single x single (1 MMA per k16-step).
// 128x64 tiles, cp.async 3-stage ring, ONE sync per K-iteration, 3 CTAs/SM.
// ---------------------------------------------------------------------------
#define E3_STAGE 15360
#define E3_SMEM  46080

__global__ __launch_bounds__(256, 3) void einsum_mma_kernel()
{
    extern __shared__ __align__(16) char esm[];
    const int tid  = threadIdx.x;
    const int lane = tid & 31;
    const int wid  = tid >> 5;
    const int d    = blockIdx.y;
    const int i0   = (blockIdx.x & 3) * 128;
    const int j0   = (blockIdx.x >> 2) * 64;
    const uint32_t sbm = smem_u32(esm);

    const __half* __restrict__ base = g_ab + (size_t)d * NN;

    uint32_t goff[3], soff[3];
    #pragma unroll
    for (int it = 0; it < 3; ++it) {
        int arr, rem;
        if (it < 2) { arr = 0; rem = it * 256 + tid; }
        else        { arr = 1; rem = tid; }
        const int row = rem >> 2, seg = rem & 3;
        const int r0 = (arr == 0) ? i0 : j0;
        const uint32_t ab = (arr == 0) ? 0u : 10240u;
        goff[it] = (uint32_t)(arr * ARRSZ) + (uint32_t)((r0 + row)*512 + seg*8);
        soff[it] = ab + (uint32_t)(row*80 + seg*16);
    }

    const int g = lane >> 3, r = lane & 7;
    const int wm = (wid & 3) * 32;
    const int wn = (wid >> 2) * 32;
    uint32_t aoff[2], boff[2];
    #pragma unroll
    for (int mi = 0; mi < 2; ++mi)
        aoff[mi] = sbm + (uint32_t)((wm + mi*16 + r + (g&1)*8)*80 + ((g>>1)*8)*2);
    #pragma unroll
    for (int p = 0; p < 2; ++p)
        boff[p] = sbm + 10240 + (uint32_t)((wn + p*16 + r + (g>>1)*8)*80 + ((g&1)*8)*2);

    float acc[2][4][4] = {};

    #pragma unroll
    for (int it = 0; it < 3; ++it)
        CPASYNC16(sbm + soff[it], base + goff[it]);
    CPCOMMIT();
    #pragma unroll
    for (int it = 0; it < 3; ++it)
        CPASYNC16(sbm + E3_STAGE + soff[it], base + goff[it] + 32);
    CPCOMMIT();

    #pragma unroll 1
    for (int kc = 0; kc < 16; ++kc) {
        if (kc < 15) { CPWAIT1(); } else { CPWAIT0(); }
        __syncthreads();

        if (kc < 14) {
            const uint32_t nstg = (uint32_t)((kc + 2) % 3) * E3_STAGE;
            const int kb = (kc + 2) * 32;
            #pragma unroll
            for (int it = 0; it < 3; ++it)
                CPASYNC16(sbm + nstg + soff[it], base + goff[it] + kb);
            CPCOMMIT();
        }

        const uint32_t stg = (uint32_t)(kc % 3) * E3_STAGE;
        #pragma unroll
        for (int ks2 = 0; ks2 < 2; ++ks2) {
            const uint32_t off = stg + (uint32_t)ks2 * 32;
            uint32_t A[2][4], B[2][4];
            #pragma unroll
            for (int mi = 0; mi < 2; ++mi)
                ldm4(A[mi], aoff[mi] + off);
            #pragma unroll
            for (int p = 0; p < 2; ++p)
                ldm4(B[p], boff[p] + off);
            #pragma unroll
            for (int mi = 0; mi < 2; ++mi)
                #pragma unroll
                for (int ni = 0; ni < 4; ++ni) {
                    const int p = ni >> 1, h = (ni & 1) * 2;
                    mma_f16(acc[mi][ni], A[mi], B[p][h], B[p][h+1]);
                }
        }
    }
    __syncthreads();

    float* smT = (float*)esm;   // [64][132]
    #pragma unroll
    for (int mi = 0; mi < 2; ++mi)
        #pragma unroll
        for (int ni = 0; ni < 4; ++ni) {
            const int m = wm + mi*16 + (lane >> 2);
            const int j = wn + ni*8 + (lane & 3)*2;
            smT[(j  )*132 + m    ] = acc[mi][ni][0];
            smT[(j+1)*132 + m    ] = acc[mi][ni][1];
            smT[(j  )*132 + m + 8] = acc[mi][ni][2];
            smT[(j+1)*132 + m + 8] = acc[mi][ni][3];
        }
    __syncthreads();

    __half* gm = g_mix + (size_t)d * NN;
    #pragma unroll
    for (int it = 0; it < 8; ++it) {
        const int idx = it*256 + tid;
        const int j = idx >> 5, c4 = idx & 31;
        __half2 h0 = __floats2half2_rn(smT[j*132 + c4*4 + 0], smT[j*132 + c4*4 + 1]);
        __half2 h1 = __floats2half2_rn(smT[j*132 + c4*4 + 2], smT[j*132 + c4*4 + 3]);
        uint2 o;
        *(__half2*)&o.x = h0;
        *(__half2*)&o.y = h1;
        *(uint2*)(gm + (size_t)(j0 + j)*512 + i0 + c4*4) = o;
    }
}

// ---------------------------------------------------------------------------
// Kernel 3: out-LN (over d) * out_gate, then @ W_out + b_out — single-A fp16.
// g_mix fp16 read twice (2nd hits L2). 4 CTAs/SM.
// ---------------------------------------------------------------------------
#define O_AH    0
#define O_RED   17408
#define O_SMEM  36864      // stage [64][132] f32 = 33792 overlays AH+red

__global__ __launch_bounds__(256, 4) void out_mma_kernel(
    const float* __restrict__ gs, const float* __restrict__ gb,
    const float* __restrict__ bout, float* __restrict__ out)
{
    extern __shared__ __align__(16) char sm3[];
    const int tid  = threadIdx.x;
    const int lane = tid & 31;
    const int wid  = tid >> 5;
    const int rt0  = blockIdx.x * 64;
    const int j    = rt0 >> 9;
    const int ibase = rt0 & 511;
    const uint32_t sb = smem_u32(sm3);

    float* red = (float*)(sm3 + O_RED);

    const int rt_l = tid & 63;
    const int qtr  = tid >> 6;
    const int d0   = qtr * 32;

    float s = 0.f, q = 0.f;
    #pragma unroll 8
    for (int dd = d0; dd < d0 + 32; ++dd) {
        float v = __half2float(g_mix[(size_t)dd*NN + rt0 + rt_l]);
        s += v; q += v*v;
    }
    red[qtr*64 + rt_l]       = s;
    red[256 + qtr*64 + rt_l] = q;
    __syncthreads();
    const float S = red[rt_l] + red[64 + rt_l] + red[128 + rt_l] + red[192 + rt_l];
    const float Q = red[256 + rt_l] + red[320 + rt_l] + red[384 + rt_l] + red[448 + rt_l];
    const float mu   = S * (1.f/128.f);
    const float rstd = rsqrtf(Q * (1.f/128.f) - mu*mu + 1e-6f);

    #pragma unroll 4
    for (int dd = d0; dd < d0 + 32; dd += 2) {
        float v0 = __half2float(g_mix[(size_t) dd     *NN + rt0 + rt_l]);
        float v1 = __half2float(g_mix[(size_t)(dd + 1)*NN + rt0 + rt_l]);
        float o0 = __half2float(g_og[(size_t) dd     *NN + rt0 + rt_l]);
        float o1 = __half2float(g_og[(size_t)(dd + 1)*NN + rt0 + rt_l]);
        float g0 = ((v0 - mu)*rstd*__ldg(gs+dd)   + __ldg(gb+dd))   * o0;
        float g1 = ((v1 - mu)*rstd*__ldg(gs+dd+1) + __ldg(gb+dd+1)) * o1;
        __half2 h2 = __floats2half2_rn(g0, g1);
        *(__half2*)(sm3 + O_AH + rt_l*272 + dd*2) = h2;
    }
    __syncthreads();

    const int g = lane >> 3, r = lane & 7;
    const int wm = (wid & 1) * 32;
    const int wn = (wid >> 1) * 32;
    uint32_t aoffH[2];
    #pragma unroll
    for (int mi = 0; mi < 2; ++mi)
        aoffH[mi] = sb + O_AH +
            (uint32_t)((wm + mi*16 + r + (g&1)*8) * 272 + ((g>>1)*8)*2);
    const uint4* __restrict__ fw = g_wfrag + 5 * 2048 + lane;
    const int pbase = wn >> 4;

    float acc[2][4][4] = {};
    #pragma unroll
    for (int kc = 0; kc < 8; ++kc) {
        uint32_t AH[2][4];
        #pragma unroll
        for (int mi = 0; mi < 2; ++mi)
            ldm4(AH[mi], aoffH[mi] + kc*32);
        #pragma unroll
        for (int p4 = 0; p4 < 2; ++p4) {
            const uint4 bh = fw[(kc*8 + pbase + p4) * 32];
            #pragma unroll
            for (int ns = 0; ns < 2; ++ns) {
                const int ni = p4*2 + ns;
                const uint32_t h0 = ns ? bh.z : bh.x, h1 = ns ? bh.w : bh.y;
                #pragma unroll
                for (int mi = 0; mi < 2; ++mi)
                    mma_f16(acc[mi][ni], AH[mi], h0, h1);
            }
        }
    }
    __syncthreads();   // A reads done; stage overlays AH+red region

    float* stagef = (float*)(sm3 + O_AH);   // [64][132] f32
    #pragma unroll
    for (int mi = 0; mi < 2; ++mi)
        #pragma unroll
        for (int ni = 0; ni < 4; ++ni) {
            const int m0 = wm + mi*16 + (lane >> 2);
            const int n  = wn + ni*8 + (lane & 3)*2;
            const float b0 = __ldg(bout + n), b1 = __ldg(bout + n + 1);
            stagef[ m0   *132 + n    ] = acc[mi][ni][0] + b0;
            stagef[ m0   *132 + n + 1] = acc[mi][ni][1] + b1;
            stagef[(m0+8)*132 + n    ] = acc[mi][ni][2] + b0;
            stagef[(m0+8)*132 + n + 1] = acc[mi][ni][3] + b1;
        }
    __syncthreads();

    #pragma unroll
    for (int it = 0; it < 8; ++it) {
        const int idx = it * 256 + tid;
        const int row = idx >> 5, c4 = idx & 31;
        float4 v;
        v.x = stagef[row*132 + c4*4 + 0];
        v.y = stagef[row*132 + c4*4 + 1];
        v.z = stagef[row*132 + c4*4 + 2];
        v.w = stagef[row*132 + c4*4 + 3];
        *reinterpret_cast<float4*>(
            out + ((size_t)(ibase + row)*512 + j)*DD + c4*4) = v;
    }
}

// ---------------------------------------------------------------------------
extern "C" void kernel_launch(void* const* d_in, const int* in_sizes, int n_in,
                              void* d_out, int out_size)
{
    const float* x    = (const float*)d_in[0];
    const float* mskp = (const float*)d_in[1];
    const float* nsc  = (const float*)d_in[2];
    const float* nbi  = (const float*)d_in[3];
    const float* Wl   = (const float*)d_in[4];
    const float* bl   = (const float*)d_in[5];
    const float* Wr   = (const float*)d_in[6];
    const float* br   = (const float*)d_in[7];
    const float* Wlg  = (const float*)d_in[8];
    const float* blg  = (const float*)d_in[9];
    const float* Wrg  = (const float*)d_in[10];
    const float* brg  = (const float*)d_in[11];
    const float* Wog  = (const float*)d_in[12];
    const float* bog  = (const float*)d_in[13];
    const float* gs   = (const float*)d_in[14];
    const float* gb   = (const float*)d_in[15];
    const float* Wout = (const float*)d_in[16];
    const float* bout = (const float*)d_in[17];
    float* out = (float*)d_out;

    cudaFuncSetAttribute(einsum_mma_kernel,
                         cudaFuncAttributeMaxDynamicSharedMemorySize, E3_SMEM);
    cudaFuncSetAttribute(ln_proj_mma_kernel,
                         cudaFuncAttributeMaxDynamicSharedMemorySize, K1_SMEM);
    cudaFuncSetAttribute(out_mma_kernel,
                         cudaFuncAttributeMaxDynamicSharedMemorySize, O_SMEM);

    wprep_kernel<<<6, 256>>>(Wlg, Wl, Wrg, Wr, Wog, Wout);
    ln_proj_mma_kernel<<<4096, 256, K1_SMEM>>>(x, mskp, nsc, nbi,
                                               bl, br, blg, brg, bog);
    einsum_mma_kernel<<<dim3(32, 128), 256, E3_SMEM>>>();
    out_mma_kernel<<<4096, 256, O_SMEM>>>(gs, gb, bout, out);
}

// round 17
// speedup vs baseline: 1.6601x; 1.0268x over previous
#include <cuda_runtime.h>
#include <cuda_bf16.h>
#include <cuda_fp16.h>
#include <math.h>
#include <stdint.h>

// Problem constants
#define NTOK 512
#define DD   128
#define NN   (NTOK*NTOK)

// Scratch (static __device__ arrays — no allocation allowed)
//   g_ab[arr][c][row*512+k] fp16: arr 0=left 1=right (single-rounded)
//   g_og  [c][j*512+i] fp16 sigmoid(out-gate)
//   g_mix [d][j*512+i] einsum result fp16
//   g_wfrag[w][kc][p][lane] uint4 — fp16 B-fragment-ready weights
__device__ __half        g_ab [67108864];
__device__ __half        g_og [33554432];
__device__ __half        g_mix[33554432];
__device__ __align__(16) uint4 g_wfrag[6 * 2048];

#define ARRSZ (128*NN)

// ---------------------------------------------------------------------------
// helpers
// ---------------------------------------------------------------------------
__device__ __forceinline__ uint32_t smem_u32(const void* p) {
    uint32_t a;
    asm("{ .reg .u64 t; cvta.to.shared.u64 t, %1; cvt.u32.u64 %0, t; }"
        : "=r"(a) : "l"(p));
    return a;
}

__device__ __forceinline__ void ldm4(uint32_t r[4], uint32_t addr) {
    asm volatile("ldmatrix.sync.aligned.m8n8.x4.shared.b16 {%0,%1,%2,%3}, [%4];"
                 : "=r"(r[0]), "=r"(r[1]), "=r"(r[2]), "=r"(r[3]) : "r"(addr));
}

__device__ __forceinline__ void mma_f16(float acc[4], const uint32_t a[4],
                                        uint32_t b0, uint32_t b1) {
    asm volatile(
        "mma.sync.aligned.m16n8k16.row.col.f32.f16.f16.f32 "
        "{%0,%1,%2,%3}, {%4,%5,%6,%7}, {%8,%9}, {%0,%1,%2,%3};"
        : "+f"(acc[0]), "+f"(acc[1]), "+f"(acc[2]), "+f"(acc[3])
        : "r"(a[0]), "r"(a[1]), "r"(a[2]), "r"(a[3]), "r"(b0), "r"(b1));
}

#define CPASYNC16(dst, src) \
    asm volatile("cp.async.cg.shared.global [%0], [%1], 16;" \
                 :: "r"(dst), "l"(src) : "memory")
#define CPCOMMIT() asm volatile("cp.async.commit_group;" ::: "memory")
#define CPWAIT1()  asm volatile("cp.async.wait_group 1;" ::: "memory")
#define CPWAIT0()  asm volatile("cp.async.wait_group 0;" ::: "memory")

__device__ __forceinline__ float sigmoidf_(float z) {
    return 1.f / (1.f + expf(-z));
}

// ---------------------------------------------------------------------------
// Kernel 0: weights -> fp16 B-fragment layout, register-ready for mma.sync.
// ---------------------------------------------------------------------------
__global__ void wprep_kernel(const float* __restrict__ W0, const float* __restrict__ W1,
                             const float* __restrict__ W2, const float* __restrict__ W3,
                             const float* __restrict__ W4, const float* __restrict__ W5)
{
    const float* W = (blockIdx.x == 0) ? W0 : (blockIdx.x == 1) ? W1 :
                     (blockIdx.x == 2) ? W2 : (blockIdx.x == 3) ? W3 :
                     (blockIdx.x == 4) ? W4 : W5;
    uint4* dst = g_wfrag + blockIdx.x * 2048;
    for (int idx = threadIdx.x; idx < 2048; idx += 256) {
        const int lane = idx & 31;
        const int p    = (idx >> 5) & 7;
        const int kc   = idx >> 8;
        const int nf = p * 16 + (lane >> 2);
        const int k0 = kc * 16 + 2 * (lane & 3);
        uint16_t e[8];
        #pragma unroll
        for (int q = 0; q < 8; ++q) {
            const int k = k0 + (q & 1) + ((q >> 1) & 1) * 8;
            const int n = nf + (q >> 2) * 8;
            __half h = __float2half_rn(W[k * 128 + n]);
            e[q] = *(uint16_t*)&h;
        }
        uint4 o;
        o.x = (uint32_t)e[0] | ((uint32_t)e[1] << 16);
        o.y = (uint32_t)e[2] | ((uint32_t)e[3] << 16);
        o.z = (uint32_t)e[4] | ((uint32_t)e[5] << 16);
        o.w = (uint32_t)e[6] | ((uint32_t)e[7] << 16);
        dst[idx] = o;
    }
}

// ---------------------------------------------------------------------------
// Kernel 1: LayerNorm + 5 projections (fp16 single-A MMA, fused value+gate).
// 64-row blocks, 8 warps 2m x 4n (warp tile 32x32), 2 CTAs/SM.
// (Round-15 proven config; 16-col warp tiles under-cover with 8 warps.)
// MODE: 1 = value+gate (store gated value single fp16), 2 = out-gate
// ---------------------------------------------------------------------------
#define K1_AH   0
#define K1_ST   17408
#define K1_MS   50432
#define K1_SMEM 50688

template<int MODE>
__device__ __forceinline__ void k1_pass2(
    char* sm1, uint32_t sb, int wv, int wg,
    const float* __restrict__ bv, const float* __restrict__ bg,
    int tid, int lane, int wm, int wn,
    __half* dst, size_t gbase)
{
    constexpr bool PAIR = (MODE == 1);
    const int g = lane >> 3, r = lane & 7;
    uint32_t aoffH[2];
    #pragma unroll
    for (int mi = 0; mi < 2; ++mi)
        aoffH[mi] = sb + K1_AH +
            (uint32_t)((wm + mi*16 + r + (g&1)*8) * 272 + ((g>>1)*8)*2);
    const uint4* __restrict__ fv = g_wfrag + wv * 2048 + lane;
    const uint4* __restrict__ fg = g_wfrag + wg * 2048 + lane;
    const int pbase = wn >> 4;

    float accV[2][4][4] = {};
    float accG[PAIR ? 2 : 1][4][4] = {};

    #pragma unroll
    for (int kc = 0; kc < 8; ++kc) {
        uint32_t AH[2][4];
        #pragma unroll
        for (int mi = 0; mi < 2; ++mi)
            ldm4(AH[mi], aoffH[mi] + kc*32);
        #pragma unroll
        for (int p4 = 0; p4 < 2; ++p4) {
            const int fidx = (kc*8 + pbase + p4) * 32;
            const uint4 bv4 = fv[fidx];
            uint4 bg4;
            if (PAIR) bg4 = fg[fidx];
            #pragma unroll
            for (int ns = 0; ns < 2; ++ns) {
                const int ni = p4*2 + ns;
                const uint32_t v0 = ns ? bv4.z : bv4.x, v1 = ns ? bv4.w : bv4.y;
                #pragma unroll
                for (int mi = 0; mi < 2; ++mi)
                    mma_f16(accV[mi][ni], AH[mi], v0, v1);
                if (PAIR) {
                    const uint32_t g0 = ns ? bg4.z : bg4.x, g1 = ns ? bg4.w : bg4.y;
                    #pragma unroll
                    for (int mi = 0; mi < 2; ++mi)
                        mma_f16(accG[mi][ni], AH[mi], g0, g1);
                }
            }
        }
    }

    float* stagef = (float*)(sm1 + K1_ST);
    const float* mask_s = (const float*)(sm1 + K1_MS);

    #pragma unroll
    for (int mi = 0; mi < 2; ++mi)
        #pragma unroll
        for (int ni = 0; ni < 4; ++ni) {
            const int m0 = wm + mi*16 + (lane >> 2);
            const int n  = wn + ni*8 + (lane & 3)*2;
            const float b0 = __ldg(bv + n), b1 = __ldg(bv + n + 1);
            float* a = accV[mi][ni];
            if (PAIR) {
                const float c0 = __ldg(bg + n), c1 = __ldg(bg + n + 1);
                const float* gacc = accG[mi][ni];
                const float mk0 = mask_s[m0], mk1 = mask_s[m0 + 8];
                stagef[ m0   *129 + n    ] = (a[0]+b0)*mk0*sigmoidf_(gacc[0]+c0);
                stagef[ m0   *129 + n + 1] = (a[1]+b1)*mk0*sigmoidf_(gacc[1]+c1);
                stagef[(m0+8)*129 + n    ] = (a[2]+b0)*mk1*sigmoidf_(gacc[2]+c0);
                stagef[(m0+8)*129 + n + 1] = (a[3]+b1)*mk1*sigmoidf_(gacc[3]+c1);
            } else {
                stagef[ m0   *129 + n    ] = sigmoidf_(a[0] + b0);
                stagef[ m0   *129 + n + 1] = sigmoidf_(a[1] + b1);
                stagef[(m0+8)*129 + n    ] = sigmoidf_(a[2] + b0);
                stagef[(m0+8)*129 + n + 1] = sigmoidf_(a[3] + b1);
            }
        }
    __syncthreads();

    #pragma unroll
    for (int it = 0; it < 8; ++it) {
        const int idx = it * 256 + tid;        // 2048 = 128c x 16 row-quads
        const int c  = idx >> 4;
        const int rq = (idx & 15) * 4;
        __half2 a = __floats2half2_rn(stagef[(rq  )*129 + c], stagef[(rq+1)*129 + c]);
        __half2 b = __floats2half2_rn(stagef[(rq+2)*129 + c], stagef[(rq+3)*129 + c]);
        uint2 o;
        *(__half2*)&o.x = a;
        *(__half2*)&o.y = b;
        *(uint2*)(dst + (size_t)c * NN + gbase + rq) = o;
    }
    __syncthreads();
}

__global__ __launch_bounds__(256, 2) void ln_proj_mma_kernel(
    const float* __restrict__ x,   const float* __restrict__ msk,
    const float* __restrict__ nsc, const float* __restrict__ nbi,
    const float* __restrict__ bl,  const float* __restrict__ br,
    const float* __restrict__ blg, const float* __restrict__ brg,
    const float* __restrict__ bog)
{
    extern __shared__ __align__(16) char sm1[];
    const int tid  = threadIdx.x;
    const int lane = tid & 31;
    const int wid  = tid >> 5;
    const int n2   = blockIdx.x & 511;
    const int n1b  = (blockIdx.x >> 9) << 6;
    const uint32_t sb = smem_u32(sm1);

    // ---- LayerNorm prologue: single fp16 A into smem ----
    {
        const int row = tid >> 2, sub = tid & 3;
        const float4* xr = reinterpret_cast<const float4*>(
                               x + ((size_t)(n1b + row) * 512 + n2) * DD) + sub * 8;
        float4 v[8];
        float s = 0.f, ss = 0.f;
        #pragma unroll
        for (int q = 0; q < 8; ++q) {
            v[q] = xr[q];
            s  += v[q].x + v[q].y + v[q].z + v[q].w;
            ss += v[q].x*v[q].x + v[q].y*v[q].y + v[q].z*v[q].z + v[q].w*v[q].w;
        }
        s  += __shfl_xor_sync(0xffffffffu, s, 1);
        ss += __shfl_xor_sync(0xffffffffu, ss, 1);
        s  += __shfl_xor_sync(0xffffffffu, s, 2);
        ss += __shfl_xor_sync(0xffffffffu, ss, 2);
        const float mu   = s * (1.f/128.f);
        const float var  = ss * (1.f/128.f) - mu*mu;
        const float rstd = rsqrtf(var + 1e-6f);
        #pragma unroll
        for (int q = 0; q < 8; ++q) {
            const int d0 = sub*32 + q*4;
            float a0 = (v[q].x - mu)*rstd*__ldg(&nsc[d0+0]) + __ldg(&nbi[d0+0]);
            float a1 = (v[q].y - mu)*rstd*__ldg(&nsc[d0+1]) + __ldg(&nbi[d0+1]);
            float a2 = (v[q].z - mu)*rstd*__ldg(&nsc[d0+2]) + __ldg(&nbi[d0+2]);
            float a3 = (v[q].w - mu)*rstd*__ldg(&nsc[d0+3]) + __ldg(&nbi[d0+3]);
            __half2 h01 = __floats2half2_rn(a0, a1);
            __half2 h23 = __floats2half2_rn(a2, a3);
            uint2 hw;
            *(__half2*)&hw.x = h01;
            *(__half2*)&hw.y = h23;
            *(uint2*)(sm1 + K1_AH + row*272 + d0*2) = hw;
        }
        if (sub == 0)
            ((float*)(sm1 + K1_MS))[row] = msk[n1b + row] * msk[n2];
    }
    __syncthreads();

    const int wm = (wid & 1) * 32;
    const int wn = (wid >> 1) * 32;
    const size_t gbase = (size_t)n2 * 512 + n1b;

    k1_pass2<1>(sm1, sb, 1, 0, bl,  blg, tid, lane, wm, wn, g_ab,         gbase);
    k1_pass2<1>(sm1, sb, 3, 2, br,  brg, tid, lane, wm, wn, g_ab + ARRSZ, gbase);
    k1_pass2<2>(sm1, sb, 4, 4, bog, bog, tid, lane, wm, wn, g_og,         gbase);
}

// ---------------------------------------------------------------------------
// Kernel 2: einsum via mma.sync fp16 single x single, 128x128 tiles.
// 8 warps 4m x 2n (warp 32x64, acc 64 regs; ~115 live < 128-reg cap at
// minBlocks=2). cp.async 3-stage ring, one sync per K-iter, 2 CTAs/SM.
// Epilogue transposes in two 64-row halves.
// ---------------------------------------------------------------------------
#define E3_STAGE 20480
#define E3_SMEM  61440

__global__ __launch_bounds__(256, 2) void einsum_mma_kernel()
{
    extern __shared__ __align__(16) char esm[];
    const int tid  = threadIdx.x;
    const int lane = tid & 31;
    const int wid  = tid >> 5;
    const int d    = blockIdx.y;
    const int i0   = (blockIdx.x & 3) * 128;
    const int j0   = (blockIdx.x >> 2) * 128;
    const uint32_t sbm = smem_u32(esm);

    const __half* __restrict__ base = g_ab + (size_t)d * NN;

    // 4 transfers per chunk: A 2x256thr (128 rows), B 2x256thr (128 rows)
    uint32_t goff[4], soff[4];
    #pragma unroll
    for (int it = 0; it < 4; ++it) {
        const int arr = it >> 1;
        const int rem = (it & 1) * 256 + tid;
        const int row = rem >> 2, seg = rem & 3;
        const int r0 = (arr == 0) ? i0 : j0;
        const uint32_t ab = (arr == 0) ? 0u : 10240u;
        goff[it] = (uint32_t)(arr * ARRSZ) + (uint32_t)((r0 + row)*512 + seg*8);
        soff[it] = ab + (uint32_t)(row*80 + seg*16);
    }

    const int g = lane >> 3, r = lane & 7;
    const int wm = (wid & 3) * 32;
    const int wn = (wid >> 2) * 64;
    uint32_t aoff[2], boff[4];
    #pragma unroll
    for (int mi = 0; mi < 2; ++mi)
        aoff[mi] = sbm + (uint32_t)((wm + mi*16 + r + (g&1)*8)*80 + ((g>>1)*8)*2);
    #pragma unroll
    for (int p = 0; p < 4; ++p)
        boff[p] = sbm + 10240 + (uint32_t)((wn + p*16 + r + (g>>1)*8)*80 + ((g&1)*8)*2);

    float acc[2][8][4] = {};

    #pragma unroll
    for (int it = 0; it < 4; ++it)
        CPASYNC16(sbm + soff[it], base + goff[it]);
    CPCOMMIT();
    #pragma unroll
    for (int it = 0; it < 4; ++it)
        CPASYNC16(sbm + E3_STAGE + soff[it], base + goff[it] + 32);
    CPCOMMIT();

    #pragma unroll 1
    for (int kc = 0; kc < 16; ++kc) {
        if (kc < 15) { CPWAIT1(); } else { CPWAIT0(); }
        __syncthreads();

        if (kc < 14) {
            const uint32_t nstg = (uint32_t)((kc + 2) % 3) * E3_STAGE;
            const int kb = (kc + 2) * 32;
            #pragma unroll
            for (int it = 0; it < 4; ++it)
                CPASYNC16(sbm + nstg + soff[it], base + goff[it] + kb);
            CPCOMMIT();
        }

        const uint32_t stg = (uint32_t)(kc % 3) * E3_STAGE;
        #pragma unroll
        for (int ks2 = 0; ks2 < 2; ++ks2) {
            const uint32_t off = stg + (uint32_t)ks2 * 32;
            uint32_t A[2][4], B[4][4];
            #pragma unroll
            for (int mi = 0; mi < 2; ++mi)
                ldm4(A[mi], aoff[mi] + off);
            #pragma unroll
            for (int p = 0; p < 4; ++p)
                ldm4(B[p], boff[p] + off);
            #pragma unroll
            for (int mi = 0; mi < 2; ++mi)
                #pragma unroll
                for (int ni = 0; ni < 8; ++ni) {
                    const int p = ni >> 1, h = (ni & 1) * 2;
                    mma_f16(acc[mi][ni], A[mi], B[p][h], B[p][h+1]);
                }
        }
    }

    // epilogue: two 64-row halves through smT [64][132]
    float* smT = (float*)esm;
    __half* gm = g_mix + (size_t)d * NN;
    #pragma unroll
    for (int half = 0; half < 2; ++half) {
        __syncthreads();
        if ((wid >> 2) == half) {
            #pragma unroll
            for (int mi = 0; mi < 2; ++mi)
                #pragma unroll
                for (int ni = 0; ni < 8; ++ni) {
                    const int m = wm + mi*16 + (lane >> 2);
                    const int jl = ni*8 + (lane & 3)*2;
                    smT[(jl  )*132 + m    ] = acc[mi][ni][0];
                    smT[(jl+1)*132 + m    ] = acc[mi][ni][1];
                    smT[(jl  )*132 + m + 8] = acc[mi][ni][2];
                    smT[(jl+1)*132 + m + 8] = acc[mi][ni][3];
                }
        }
        __syncthreads();
        #pragma unroll
        for (int it = 0; it < 8; ++it) {
            const int idx = it*256 + tid;      // 64 rows x 32 quads
            const int jl = idx >> 5, c4 = idx & 31;
            __half2 h0 = __floats2half2_rn(smT[jl*132 + c4*4 + 0], smT[jl*132 + c4*4 + 1]);
            __half2 h1 = __floats2half2_rn(smT[jl*132 + c4*4 + 2], smT[jl*132 + c4*4 + 3]);
            uint2 o;
            *(__half2*)&o.x = h0;
            *(__half2*)&o.y = h1;
            *(uint2*)(gm + (size_t)(j0 + half*64 + jl)*512 + i0 + c4*4) = o;
        }
    }
}

// ---------------------------------------------------------------------------
// Kernel 3: out-LN (over d) * out_gate, then @ W_out + b_out — single-A fp16.
// g_mix fp16 read twice (2nd hits L2). 4 CTAs/SM.
// ---------------------------------------------------------------------------
#define O_AH    0
#define O_RED   17408
#define O_SMEM  36864      // stage [64][132] f32 = 33792 overlays AH+red

__global__ __launch_bounds__(256, 4) void out_mma_kernel(
    const float* __restrict__ gs, const float* __restrict__ gb,
    const float* __restrict__ bout, float* __restrict__ out)
{
    extern __shared__ __align__(16) char sm3[];
    const int tid  = threadIdx.x;
    const int lane = tid & 31;
    const int wid  = tid >> 5;
    const int rt0  = blockIdx.x * 64;
    const int j    = rt0 >> 9;
    const int ibase = rt0 & 511;
    const uint32_t sb = smem_u32(sm3);

    float* red = (float*)(sm3 + O_RED);

    const int rt_l = tid & 63;
    const int qtr  = tid >> 6;
    const int d0   = qtr * 32;

    float s = 0.f, q = 0.f;
    #pragma unroll 8
    for (int dd = d0; dd < d0 + 32; ++dd) {
        float v = __half2float(g_mix[(size_t)dd*NN + rt0 + rt_l]);
        s += v; q += v*v;
    }
    red[qtr*64 + rt_l]       = s;
    red[256 + qtr*64 + rt_l] = q;
    __syncthreads();
    const float S = red[rt_l] + red[64 + rt_l] + red[128 + rt_l] + red[192 + rt_l];
    const float Q = red[256 + rt_l] + red[320 + rt_l] + red[384 + rt_l] + red[448 + rt_l];
    const float mu   = S * (1.f/128.f);
    const float rstd = rsqrtf(Q * (1.f/128.f) - mu*mu + 1e-6f);

    #pragma unroll 4
    for (int dd = d0; dd < d0 + 32; dd += 2) {
        float v0 = __half2float(g_mix[(size_t) dd     *NN + rt0 + rt_l]);
        float v1 = __half2float(g_mix[(size_t)(dd + 1)*NN + rt0 + rt_l]);
        float o0 = __half2float(g_og[(size_t) dd     *NN + rt0 + rt_l]);
        float o1 = __half2float(g_og[(size_t)(dd + 1)*NN + rt0 + rt_l]);
        float g0 = ((v0 - mu)*rstd*__ldg(gs+dd)   + __ldg(gb+dd))   * o0;
        float g1 = ((v1 - mu)*rstd*__ldg(gs+dd+1) + __ldg(gb+dd+1)) * o1;
        __half2 h2 = __floats2half2_rn(g0, g1);
        *(__half2*)(sm3 + O_AH + rt_l*272 + dd*2) = h2;
    }
    __syncthreads();

    const int g = lane >> 3, r = lane & 7;
    const int wm = (wid & 1) * 32;
    const int wn = (wid >> 1) * 32;
    uint32_t aoffH[2];
    #pragma unroll
    for (int mi = 0; mi < 2; ++mi)
        aoffH[mi] = sb + O_AH +
            (uint32_t)((wm + mi*16 + r + (g&1)*8) * 272 + ((g>>1)*8)*2);
    const uint4* __restrict__ fw = g_wfrag + 5 * 2048 + lane;
    const int pbase = wn >> 4;

    float acc[2][4][4] = {};
    #pragma unroll
    for (int kc = 0; kc < 8; ++kc) {
        uint32_t AH[2][4];
        #pragma unroll
        for (int mi = 0; mi < 2; ++mi)
            ldm4(AH[mi], aoffH[mi] + kc*32);
        #pragma unroll
        for (int p4 = 0; p4 < 2; ++p4) {
            const uint4 bh = fw[(kc*8 + pbase + p4) * 32];
            #pragma unroll
            for (int ns = 0; ns < 2; ++ns) {
                const int ni = p4*2 + ns;
                const uint32_t h0 = ns ? bh.z : bh.x, h1 = ns ? bh.w : bh.y;
                #pragma unroll
                for (int mi = 0; mi < 2; ++mi)
                    mma_f16(acc[mi][ni], AH[mi], h0, h1);
            }
        }
    }
    __syncthreads();   // A reads done; stage overlays AH+red region

    float* stagef = (float*)(sm3 + O_AH);   // [64][132] f32
    #pragma unroll
    for (int mi = 0; mi < 2; ++mi)
        #pragma unroll
        for (int ni = 0; ni < 4; ++ni) {
            const int m0 = wm + mi*16 + (lane >> 2);
            const int n  = wn + ni*8 + (lane & 3)*2;
            const float b0 = __ldg(bout + n), b1 = __ldg(bout + n + 1);
            stagef[ m0   *132 + n    ] = acc[mi][ni][0] + b0;
            stagef[ m0   *132 + n + 1] = acc[mi][ni][1] + b1;
            stagef[(m0+8)*132 + n    ] = acc[mi][ni][2] + b0;
            stagef[(m0+8)*132 + n + 1] = acc[mi][ni][3] + b1;
        }
    __syncthreads();

    #pragma unroll
    for (int it = 0; it < 8; ++it) {
        const int idx = it * 256 + tid;
        const int row = idx >> 5, c4 = idx & 31;
        float4 v;
        v.x = stagef[row*132 + c4*4 + 0];
        v.y = stagef[row*132 + c4*4 + 1];
        v.z = stagef[row*132 + c4*4 + 2];
        v.w = stagef[row*132 + c4*4 + 3];
        *reinterpret_cast<float4*>(
            out + ((size_t)(ibase + row)*512 + j)*DD + c4*4) = v;
    }
}

// ---------------------------------------------------------------------------
extern "C" void kernel_launch(void* const* d_in, const int* in_sizes, int n_in,
                              void* d_out, int out_size)
{
    const float* x    = (const float*)d_in[0];
    const float* mskp = (const float*)d_in[1];
    const float* nsc  = (const float*)d_in[2];
    const float* nbi  = (const float*)d_in[3];
    const float* Wl   = (const float*)d_in[4];
    const float* bl   = (const float*)d_in[5];
    const float* Wr   = (const float*)d_in[6];
    const float* br   = (const float*)d_in[7];
    const float* Wlg  = (const float*)d_in[8];
    const float* blg  = (const float*)d_in[9];
    const float* Wrg  = (const float*)d_in[10];
    const float* brg  = (const float*)d_in[11];
    const float* Wog  = (const float*)d_in[12];
    const float* bog  = (const float*)d_in[13];
    const float* gs   = (const float*)d_in[14];
    const float* gb   = (const float*)d_in[15];
    const float* Wout = (const float*)d_in[16];
    const float* bout = (const float*)d_in[17];
    float* out = (float*)d_out;

    cudaFuncSetAttribute(einsum_mma_kernel,
                         cudaFuncAttributeMaxDynamicSharedMemorySize, E3_SMEM);
    cudaFuncSetAttribute(ln_proj_mma_kernel,
                         cudaFuncAttributeMaxDynamicSharedMemorySize, K1_SMEM);
    cudaFuncSetAttribute(out_mma_kernel,
                         cudaFuncAttributeMaxDynamicSharedMemorySize, O_SMEM);

    wprep_kernel<<<6, 256>>>(Wlg, Wl, Wrg, Wr, Wog, Wout);
    ln_proj_mma_kernel<<<4096, 256, K1_SMEM>>>(x, mskp, nsc, nbi,
                                               bl, br, blg, brg, bog);
    einsum_mma_kernel<<<dim3(16, 128), 256, E3_SMEM>>>();
    out_mma_kernel<<<4096, 256, O_SMEM>>>(gs, gb, bout, out);
}